// round 10
// baseline (speedup 1.0000x reference)
#include <cuda_runtime.h>
#include <math.h>

#define NN 2048
#define MM 32
#define NMOM 8                 // moments M_0..M_7 (degree-7 erf series)
#define GAA 64                 // kA grid
#define TBA 512                // kA threads (16 warps), 2 elements/thread
#define NWA 16
#define GBB 128                // kB grid
#define TBB 512                // kB threads (16 warps), 1 element/thread
#define NWBB 16

// ---- scratch (no device allocations allowed) ----
__device__ float g_pmom[GAA][NMOM][MM]; // per-block raw weighted moments
__device__ float g_pmax[GAA][MM];       // per-block per-column max(diff)
__device__ float g_bco[NMOM + 1][MM];   // b_0..b_7, row NMOM = W   (built in kA tail)
__device__ float g_f[MM];               // per-column normalization factor
__device__ float g_part[GBB];           // kB per-block partial loss
__device__ int   g_cntA, g_cntB;        // election counters (reset after use)

// A[m][p] = C[(m+p-1)/2] * binom(m+p, m) * (-1)^p for (m+p) odd <= 7, else 0.
// 0.5*erf(d) ~ C0 d + C1 d^3 + C2 d^5 + C3 d^7  (|d| <= 0.3536, trunc ~5e-7 rel)
__device__ __constant__ float d_A[NMOM][NMOM] = {
  {0.f,-0.5641895835477563f,0.f, 0.18806319451591878f,0.f,-0.05641895835477563f,0.f, 0.013433085322565627f},
  {0.5641895835477563f,0.f,-0.5641895835477563f,0.f, 0.28209479177387815f,0.f,-0.09403159725795939f,0.f},
  {0.f, 0.5641895835477563f,0.f,-0.5641895835477563f,0.f, 0.28209479177387817f,0.f,0.f},
  {-0.18806319451591878f,0.f, 0.5641895835477563f,0.f,-0.47015798628979696f,0.f,0.f,0.f},
  {0.f,-0.28209479177387815f,0.f, 0.47015798628979696f,0.f,0.f,0.f,0.f},
  {0.05641895835477563f,0.f,-0.28209479177387817f,0.f,0.f,0.f,0.f,0.f},
  {0.f, 0.09403159725795939f,0.f,0.f,0.f,0.f,0.f,0.f},
  {-0.013433085322565627f,0.f,0.f,0.f,0.f,0.f,0.f,0.f}
};

// ---------------------------------------------------------------------------
// kA: moments + max partials; elected last block builds the coefficients.
// ---------------------------------------------------------------------------
__global__ void __launch_bounds__(TBA, 1) kA(const float* __restrict__ risk,
                                             const float* __restrict__ expr,
                                             const float* __restrict__ tr,
                                             const float* __restrict__ sigma) {
    const int tid  = threadIdx.x;
    const int warp = tid >> 5, lane = tid & 31;

    __shared__ float smom[NWA][NMOM][MM];   // 16 KB
    __shared__ float smax[NWA][MM];         // 2 KB
    __shared__ int   sflag;

    const int i0 = blockIdx.x * (2 * TBA) + tid;   // element 0
    const int i1 = i0 + TBA;                       // element 1 (same lane/column)

    const float d0 = expr[i0] - tr[i0];
    const float d1 = expr[i1] - tr[i1];
    const float T0 = __expf(d0),       T1 = __expf(d1);
    float       p0 = __expf(risk[i0]), p1 = __expf(risk[i1]);

    smax[warp][lane] = fmaxf(d0, d1);
    smom[warp][0][lane] = p0 + p1;
#pragma unroll
    for (int q = 1; q < NMOM; ++q) {
        p0 *= T0; p1 *= T1;
        smom[warp][q][lane] = p0 + p1;
    }
    __syncthreads();

    if (tid < 32) {                        // column max over 16 warps
        float v = smax[0][tid];
#pragma unroll
        for (int i = 1; i < NWA; ++i) v = fmaxf(v, smax[i][tid]);
        g_pmax[blockIdx.x][tid] = v;
    }
    if (tid < NMOM * MM) {                 // moment sums over 16 warps (4-acc)
        const int q = tid >> 5, kk = tid & 31;
        float s0 = 0.f, s1 = 0.f, s2 = 0.f, s3 = 0.f;
#pragma unroll
        for (int i = 0; i < NWA; i += 4) {
            s0 += smom[i + 0][q][kk];
            s1 += smom[i + 1][q][kk];
            s2 += smom[i + 2][q][kk];
            s3 += smom[i + 3][q][kk];
        }
        g_pmom[blockIdx.x][q][kk] = (s0 + s1) + (s2 + s3);
    }

    // ---- elect last block ----
    __threadfence();
    __syncthreads();
    if (tid == 0) sflag = (atomicAdd(&g_cntA, 1) == GAA - 1);
    __syncthreads();
    if (!sflag) return;
    __threadfence();

    // ---- elected block: reduce partials -> coefficients ----
    __shared__ float sred[2][NMOM][MM];
    __shared__ float smax2[8][MM];
    __shared__ float sM[NMOM][MM];
    __shared__ float sf[MM];

    {
        const int j = tid >> 8;                    // 0..1
        const int o = tid & 255;
        const int q = o >> 5, kk = o & 31;
        float s0 = 0.f, s1 = 0.f, s2 = 0.f, s3 = 0.f;
#pragma unroll
        for (int b = 0; b < GAA / 2; b += 4) {     // 32 loads, 4 accumulators
            s0 += g_pmom[j * (GAA / 2) + b + 0][q][kk];
            s1 += g_pmom[j * (GAA / 2) + b + 1][q][kk];
            s2 += g_pmom[j * (GAA / 2) + b + 2][q][kk];
            s3 += g_pmom[j * (GAA / 2) + b + 3][q][kk];
        }
        sred[j][q][kk] = (s0 + s1) + (s2 + s3);
    }
    if (tid < 8 * MM) {                            // max partials (8 strided each)
        const int i = tid >> 5;
        float v = -1e30f;
#pragma unroll
        for (int jj = 0; jj < GAA / 8; ++jj) v = fmaxf(v, g_pmax[i + jj * 8][lane]);
        smax2[i][lane] = v;
    }
    __syncthreads();
    if (tid < 32) {
        float v = smax2[0][tid];
#pragma unroll
        for (int i = 1; i < 8; ++i) v = fmaxf(v, smax2[i][tid]);
        float scale = 1.0f / (2.0f * sigma[0] * sqrtf(2.0f));
        float f = scale * __expf(-v);
        sf[tid] = f;
        g_f[tid] = f;
    }
    __syncthreads();
    if (tid < NMOM * MM) {
        const int q = tid >> 5, kk = tid & 31;
        float s = sred[0][q][kk] + sred[1][q][kk];
        float f = sf[kk], fp = 1.0f;
#pragma unroll
        for (int i = 0; i < NMOM - 1; ++i) if (i < q) fp *= f;
        sM[q][kk] = s * fp;                        // Mn_q = M'_q * f^q
    }
    __syncthreads();
    if (tid < NMOM * MM) {                         // b_m = sum_p A[m][p] * Mn_p
        const int md = tid >> 5, kk = tid & 31;
        float bm = 0.0f;
#pragma unroll
        for (int p = 0; p < NMOM; ++p) bm = fmaf(d_A[md][p], sM[p][kk], bm);
        g_bco[md][kk] = bm;
        if (md == 0) g_bco[NMOM][kk] = sM[0][kk];  // W
    }
    if (tid == 0) g_cntA = 0;                      // reset for next graph replay
}

// ---------------------------------------------------------------------------
// kB: pure eval. Coefficients broadcast from L2; one final election.
// ---------------------------------------------------------------------------
__global__ void __launch_bounds__(TBB, 1) kB(const float* __restrict__ risk,
                                             const float* __restrict__ expr,
                                             const float* __restrict__ tr,
                                             const float* __restrict__ ev,
                                             float* __restrict__ out) {
    const int tid  = threadIdx.x;
    const int warp = tid >> 5, lane = tid & 31;

    __shared__ float wred[NWBB];
    __shared__ int   sflag;

    // issue all loads up front (element data + broadcast coefficients)
    const int idx   = blockIdx.x * TBB + tid;      // lane = column
    const float rv  = risk[idx];
    const float dd  = expr[idx] - tr[idx];
    const float evv = ev[idx];

    float bb[NMOM];
#pragma unroll
    for (int q = 0; q < NMOM; ++q) bb[q] = g_bco[q][lane];
    const float W = g_bco[NMOM][lane];
    const float f = g_f[lane];

    const float T = __expf(dd);
    const float w = __expf(rv);

    float x = T * f;
    float s = bb[NMOM - 1];
#pragma unroll
    for (int q = NMOM - 2; q >= 0; --q) s = fmaf(s, x, bb[q]);
    float cum = fmaf(0.5f, W + w, -s);
    float acc = (rv - __logf(cum)) * evv;

#pragma unroll
    for (int o = 16; o > 0; o >>= 1) acc += __shfl_down_sync(0xffffffffu, acc, o);
    if (lane == 0) wred[warp] = acc;
    __syncthreads();
    if (tid == 0) {
        float b0 = 0.f, b1 = 0.f, b2 = 0.f, b3 = 0.f;
#pragma unroll
        for (int i = 0; i < NWBB; i += 4) {
            b0 += wred[i]; b1 += wred[i + 1]; b2 += wred[i + 2]; b3 += wred[i + 3];
        }
        g_part[blockIdx.x] = (b0 + b1) + (b2 + b3);
        __threadfence();
        sflag = (atomicAdd(&g_cntB, 1) == GBB - 1);
    }
    __syncthreads();
    if (!sflag) return;

    // ---- elected last block: final reduce + counter reset ----
    __threadfence();
    if (warp == 0) {
        float v = 0.0f;
#pragma unroll
        for (int i = 0; i < GBB / 32; ++i) v += g_part[lane + i * 32];
#pragma unroll
        for (int o = 16; o > 0; o >>= 1) v += __shfl_down_sync(0xffffffffu, v, o);
        if (lane == 0) {
            out[0] = -v;
            g_cntB = 0;          // safe: all blocks already passed the counter
        }
    }
}

extern "C" void kernel_launch(void* const* d_in, const int* in_sizes, int n_in,
                              void* d_out, int out_size) {
    const float* risk  = (const float*)d_in[0];
    const float* expr  = (const float*)d_in[1];
    const float* tr    = (const float*)d_in[2];
    const float* ev    = (const float*)d_in[3];
    const float* sigma = (const float*)d_in[4];
    float* out = (float*)d_out;

    kA<<<GAA, TBA>>>(risk, expr, tr, sigma);
    kB<<<GBB, TBB>>>(risk, expr, tr, ev, out);
}